// round 14
// baseline (speedup 1.0000x reference)
#include <cuda_runtime.h>
#include <math.h>

#define LSEQ   2048
#define LFFT   4096
#define DMODEL 512
#define NSTATE 64
#define NBATCH 16
#define NPAIR  (DMODEL / 2)
#define PI_F   3.14159265358979323846f

#define SWZ(i)  ((i) ^ (((i) >> 3) & 15))   // float2 swizzle (khat)
#define SW16(e) ((e) ^ (((e) >> 4) & 15))   // float2 swizzle (conv radix-16)

typedef unsigned long long ull;

__device__ float4 g_KPM4[NPAIR * LFFT];             // per pair, per bin: (P.re,P.im,M.re,M.im)
__device__ float4 g_twd[LFFT];                      // (c,s,-s,c): e^{-i pi base/Ns}
__device__ float2 g_ut[NBATCH * NPAIR * LSEQ];      // transposed input
__device__ float2 g_yt[NBATCH * NPAIR * LSEQ];      // transposed output

// ---------------- packed f32x2 helpers ----------------
__device__ __forceinline__ ull pk(float x, float y) {
    ull r; asm("mov.b64 %0, {%1,%2};" : "=l"(r) : "f"(x), "f"(y)); return r;
}
__device__ __forceinline__ void upk(ull v, float& x, float& y) {
    asm("mov.b64 {%0,%1}, %2;" : "=f"(x), "=f"(y) : "l"(v));
}
__device__ __forceinline__ ull padd(ull a, ull b) {
    ull r; asm("add.rn.f32x2 %0, %1, %2;" : "=l"(r) : "l"(a), "l"(b)); return r;
}
__device__ __forceinline__ ull pmul(ull a, ull b) {
    ull r; asm("mul.rn.f32x2 %0, %1, %2;" : "=l"(r) : "l"(a), "l"(b)); return r;
}
__device__ __forceinline__ ull pfma(ull a, ull b, ull c) {
    ull r; asm("fma.rn.f32x2 %0, %1, %2, %3;" : "=l"(r) : "l"(a), "l"(b), "l"(c)); return r;
}
__device__ __forceinline__ float frcpa(float x) {
    float r; asm("rcp.approx.f32 %0, %1;" : "=f"(r) : "f"(x)); return r;
}

__device__ __forceinline__ float2 cmulf(float2 a, float2 b) {
    return make_float2(a.x * b.x - a.y * b.y, a.x * b.y + a.y * b.x);
}
__device__ __forceinline__ float2 cadd(float2 a, float2 b) {
    union { float2 f; ull u; } A, B, R;
    A.f = a; B.f = b;
    asm("add.rn.f32x2 %0, %1, %2;" : "=l"(R.u) : "l"(A.u), "l"(B.u));
    return R.f;
}
__device__ __forceinline__ float2 csub(float2 a, float2 b) {
    union { float2 f; ull u; } A, B, R;
    A.f = a; B.f = b;
    asm("fma.rn.f32x2 %0, %1, %2, %3;"
        : "=l"(R.u) : "l"(B.u), "l"(0xBF800000BF800000ULL), "l"(A.u));
    return R.f;
}
__device__ __forceinline__ float2 cmulF(float2 v, float2 wn, float2 wr) {
    return make_float2(v.x * wn.x + v.y * wr.x, v.x * wn.y + v.y * wr.y);
}

template<bool FWD> __device__ __forceinline__ float2 mul_j(float2 a) {
    return FWD ? make_float2(a.y, -a.x) : make_float2(-a.y, a.x);
}
template<bool FWD> __device__ __forceinline__ float2 mul_w1(float2 a) {
    const float C = 0.70710678118654752f;
    return FWD ? make_float2(C * (a.x + a.y), C * (a.y - a.x))
               : make_float2(C * (a.x - a.y), C * (a.x + a.y));
}
template<bool FWD> __device__ __forceinline__ float2 mul_w3(float2 a) {
    const float C = 0.70710678118654752f;
    return FWD ? make_float2(C * (a.y - a.x), -C * (a.x + a.y))
               : make_float2(-C * (a.x + a.y), C * (a.x - a.y));
}

template<bool FWD>
__device__ __forceinline__ void fft8(float2* v) {
    float2 t0 = cadd(v[0], v[4]), t4 = csub(v[0], v[4]);
    float2 t1 = cadd(v[1], v[5]), t5 = mul_w1<FWD>(csub(v[1], v[5]));
    float2 t2 = cadd(v[2], v[6]), t6 = mul_j<FWD>(csub(v[2], v[6]));
    float2 t3 = cadd(v[3], v[7]), t7 = mul_w3<FWD>(csub(v[3], v[7]));
    float2 u0 = cadd(t0, t2), u2 = csub(t0, t2);
    float2 u1 = cadd(t1, t3), u3 = mul_j<FWD>(csub(t1, t3));
    float2 u4 = cadd(t4, t6), u6 = csub(t4, t6);
    float2 u5 = cadd(t5, t7), u7 = mul_j<FWD>(csub(t5, t7));
    v[0] = cadd(u0, u1); v[4] = csub(u0, u1);
    v[2] = cadd(u2, u3); v[6] = csub(u2, u3);
    v[1] = cadd(u4, u5); v[5] = csub(u4, u5);
    v[3] = cadd(u6, u7); v[7] = csub(u6, u7);
}

// forward fft8, inputs 4..7 == 0
__device__ __forceinline__ void fft8_z4(const float2* a, float2* v) {
    float2 t0 = a[0], t4 = a[0];
    float2 t1 = a[1], t5 = mul_w1<true>(a[1]);
    float2 t2 = a[2], t6 = mul_j<true>(a[2]);
    float2 t3 = a[3], t7 = mul_w3<true>(a[3]);
    float2 u0 = cadd(t0, t2), u2 = csub(t0, t2);
    float2 u1 = cadd(t1, t3), u3 = mul_j<true>(csub(t1, t3));
    float2 u4 = cadd(t4, t6), u6 = csub(t4, t6);
    float2 u5 = cadd(t5, t7), u7 = mul_j<true>(csub(t5, t7));
    v[0] = cadd(u0, u1); v[4] = csub(u0, u1);
    v[2] = cadd(u2, u3); v[6] = csub(u2, u3);
    v[1] = cadd(u4, u5); v[5] = csub(u4, u5);
    v[3] = cadd(u6, u7); v[7] = csub(u6, u7);
}

template<bool FWD>
__device__ __forceinline__ void fft4(float2* v) {
    float2 t0 = cadd(v[0], v[2]), t2 = csub(v[0], v[2]);
    float2 t1 = cadd(v[1], v[3]), t3 = mul_j<FWD>(csub(v[1], v[3]));
    v[0] = cadd(t0, t1); v[2] = csub(t0, t1);
    v[1] = cadd(t2, t3); v[3] = csub(t2, t3);
}

// ---------------- radix-16 building blocks (conv) ----------------
#define C16 0.92387953251128675613f
#define S16 0.38268343236508977173f

template<bool FWD>
__device__ __forceinline__ void fft16_combine(float2* E, float2* O, float2* v) {
    O[1] = cmulf(O[1], make_float2( C16, FWD ? -S16 :  S16));
    O[2] = mul_w1<FWD>(O[2]);
    O[3] = cmulf(O[3], make_float2( S16, FWD ? -C16 :  C16));
    O[4] = mul_j<FWD>(O[4]);
    O[5] = cmulf(O[5], make_float2(-S16, FWD ? -C16 :  C16));
    O[6] = mul_w3<FWD>(O[6]);
    O[7] = cmulf(O[7], make_float2(-C16, FWD ? -S16 :  S16));
#pragma unroll
    for (int k = 0; k < 8; k++) {
        v[k]     = cadd(E[k], O[k]);
        v[k + 8] = csub(E[k], O[k]);
    }
}

template<bool FWD>
__device__ __forceinline__ void fft16(float2* v) {
    float2 E[8] = {v[0], v[2], v[4], v[6], v[8], v[10], v[12], v[14]};
    float2 O[8] = {v[1], v[3], v[5], v[7], v[9], v[11], v[13], v[15]};
    fft8<FWD>(E); fft8<FWD>(O);
    fft16_combine<FWD>(E, O, v);
}

__device__ __forceinline__ void fft16_z8(const float2* x, float2* v) {
    float2 ein[4] = {x[0], x[2], x[4], x[6]};
    float2 oin[4] = {x[1], x[3], x[5], x[7]};
    float2 E[8], O[8];
    fft8_z4(ein, E);
    fft8_z4(oin, O);
    fft16_combine<true>(E, O, v);
}

__device__ __forceinline__ void fft16_lo8(float2* v, float2* o) {
    float2 E[8] = {v[0], v[2], v[4], v[6], v[8], v[10], v[12], v[14]};
    float2 O[8] = {v[1], v[3], v[5], v[7], v[9], v[11], v[13], v[15]};
    fft8<false>(E); fft8<false>(O);
    O[1] = cmulf(O[1], make_float2( C16,  S16));
    O[2] = mul_w1<false>(O[2]);
    O[3] = cmulf(O[3], make_float2( S16,  C16));
    O[4] = mul_j<false>(O[4]);
    O[5] = cmulf(O[5], make_float2(-S16,  C16));
    O[6] = mul_w3<false>(O[6]);
    O[7] = cmulf(O[7], make_float2(-C16,  S16));
#pragma unroll
    for (int k = 0; k < 8; k++) o[k] = cadd(E[k], O[k]);
}

template<bool INV>
__device__ __forceinline__ void twapply16(float2* v, float4 W1, float4 W2, float4 W4, float4 W8) {
    float2 w1n, w1r, w2n, w2r, w4n, w4r, w8n, w8r;
    if (!INV) {
        w1n = make_float2(W1.x, W1.y); w1r = make_float2(W1.z, W1.w);
        w2n = make_float2(W2.x, W2.y); w2r = make_float2(W2.z, W2.w);
        w4n = make_float2(W4.x, W4.y); w4r = make_float2(W4.z, W4.w);
        w8n = make_float2(W8.x, W8.y); w8r = make_float2(W8.z, W8.w);
    } else {
        w1n = make_float2(W1.x, -W1.y); w1r = make_float2(-W1.z, W1.w);
        w2n = make_float2(W2.x, -W2.y); w2r = make_float2(-W2.z, W2.w);
        w4n = make_float2(W4.x, -W4.y); w4r = make_float2(-W4.z, W4.w);
        w8n = make_float2(W8.x, -W8.y); w8r = make_float2(-W8.z, W8.w);
    }
    v[1] = cmulF(v[1], w1n, w1r);
    v[2] = cmulF(v[2], w2n, w2r);
    v[4] = cmulF(v[4], w4n, w4r);
    v[8] = cmulF(v[8], w8n, w8r);
    float2 w3n = cmulF(w2n, w1n, w1r), w3r = make_float2(-w3n.y, w3n.x);
    v[3] = cmulF(v[3], w3n, w3r);
    float2 w5n = cmulF(w4n, w1n, w1r), w5r = make_float2(-w5n.y, w5n.x);
    v[5] = cmulF(v[5], w5n, w5r);
    float2 w6n = cmulF(w4n, w2n, w2r), w6r = make_float2(-w6n.y, w6n.x);
    v[6] = cmulF(v[6], w6n, w6r);
    float2 w7n = cmulF(w4n, w3n, w3r), w7r = make_float2(-w7n.y, w7n.x);
    v[7] = cmulF(v[7], w7n, w7r);
    float2 w9n  = cmulF(w8n, w1n, w1r), w9r  = make_float2(-w9n.y,  w9n.x);
    v[9]  = cmulF(v[9],  w9n,  w9r);
    float2 w10n = cmulF(w8n, w2n, w2r), w10r = make_float2(-w10n.y, w10n.x);
    v[10] = cmulF(v[10], w10n, w10r);
    float2 w11n = cmulF(w8n, w3n, w3r), w11r = make_float2(-w11n.y, w11n.x);
    v[11] = cmulF(v[11], w11n, w11r);
    float2 w12n = cmulF(w8n, w4n, w4r), w12r = make_float2(-w12n.y, w12n.x);
    v[12] = cmulF(v[12], w12n, w12r);
    float2 w13n = cmulF(w8n, w5n, w5r), w13r = make_float2(-w13n.y, w13n.x);
    v[13] = cmulF(v[13], w13n, w13r);
    float2 w14n = cmulF(w8n, w6n, w6r), w14r = make_float2(-w14n.y, w14n.x);
    v[14] = cmulF(v[14], w14n, w14r);
    float2 w15n = cmulF(w8n, w7n, w7r), w15r = make_float2(-w15n.y, w15n.x);
    v[15] = cmulF(v[15], w15n, w15r);
}

// ping-pong radix-16 stage: read src, write dst, ONE barrier
template<int NS, bool INV>
__device__ __forceinline__ void stage16_pp(const float2* src, float2* dst, int t) {
    float2 v[16];
#pragma unroll
    for (int r = 0; r < 16; r++) v[r] = src[SW16(t + 256 * r)];
    const int base = t & (NS - 1);
    twapply16<INV>(v, g_twd[8 * NS + base], g_twd[4 * NS + base],
                      g_twd[2 * NS + base], g_twd[NS + base]);
    fft16<!INV>(v);
    const int idxD = ((t - base) << 4) + base;
#pragma unroll
    for (int r = 0; r < 16; r++) dst[SW16(idxD + NS * r)] = v[r];
    __syncthreads();
}

// pointwise with P/M: Y = z*P + conj(zm)*M
__device__ __forceinline__ float2 pwone_pm(float2 z, float2 zm, float2 P, float2 M) {
    return make_float2(z.x * P.x - z.y * P.y + zm.x * M.x + zm.y * M.y,
                       z.x * P.y + z.y * P.x + zm.x * M.y - zm.y * M.x);
}

// ping-pong pointwise + inverse stage 0: read src, write dst, ONE barrier
__device__ __forceinline__ void pw_inv0_pp(const float2* src, float2* dst, int t,
                                           const float4* Kp) {
    float2 v[16];
#pragma unroll
    for (int r = 0; r < 16; r++) {
        int e = t + 256 * r;
        float2 z  = src[SW16(e)];
        float2 zm = src[SW16((LFFT - e) & (LFFT - 1))];   // e=0 -> itself
        float4 K4 = Kp[e];
        v[r] = pwone_pm(z, zm, make_float2(K4.x, K4.y), make_float2(K4.z, K4.w));
    }
    fft16<false>(v);
#pragma unroll
    for (int r = 0; r < 16; r++) dst[SW16(16 * t + r)] = v[r];
    __syncthreads();
}

__global__ void init_twd_kernel() {
    int i = blockIdx.x * blockDim.x + threadIdx.x;
    if (i >= LFFT) return;
    if (i == 0) { g_twd[0] = make_float4(1.0f, 0.0f, 0.0f, 1.0f); return; }
    int k = 31 - __clz(i);
    int Ns = 1 << k;
    int base = i - Ns;
    float ang = -PI_F * (float)base / (float)Ns;
    float s, c;
    sincosf(ang, &s, &c);
    g_twd[i] = make_float4(c, s, -s, c);
}

__global__ void pad_kernel() {}

// ---------------- t2 (output transpose) ----------------
__global__ void __launch_bounds__(256) t2_kernel(float* __restrict__ out) {
    __shared__ float2 tile[32][33];
    int pt = blockIdx.x * 32;
    int rt = blockIdx.y * 32;
    int tx = threadIdx.x & 31, ty = threadIdx.x >> 5;
    int b = rt >> 11, l0 = rt & (LSEQ - 1);
#pragma unroll
    for (int i = 0; i < 4; i++) {
        int p = pt + ty + i * 8;
        tile[ty + i * 8][tx] = g_yt[((size_t)(b * NPAIR + p)) * LSEQ + l0 + tx];
    }
    __syncthreads();
    float2* of2 = reinterpret_cast<float2*>(out);
#pragma unroll
    for (int i = 0; i < 4; i++) {
        int row = ty + i * 8;
        of2[(size_t)(rt + row) * NPAIR + pt + tx] = tile[tx][row];
    }
}

// dual-channel inverse FFT2048: threads [0,256) ch0, [256,512) ch1; results in b0 halves.
__device__ void ifft2048_dual(float2* b0, float2* b1, int tid) {
    int ch = tid >> 8;
    int jt = tid & 255;
    float2* src = b0 + ch * 2048;
    float2* dst = b1 + ch * 2048;
#pragma unroll
    for (int s = 0; s < 3; s++) {
        const int Ns = 1 << (3 * s);
        {
            int j = jt;
            float2 v[8];
#pragma unroll
            for (int r = 0; r < 8; r++) v[r] = src[SWZ(j + r * 256)];
            const int base = j & (Ns - 1);
            if (Ns > 1) {
                float4 T1 = g_twd[4 * Ns + base];
                float4 T2 = g_twd[2 * Ns + base];
                float4 T4 = g_twd[Ns + base];
                float2 w1 = make_float2(T1.x, -T1.y);
                float2 w2 = make_float2(T2.x, -T2.y);
                float2 w4 = make_float2(T4.x, -T4.y);
                float2 w3 = cmulf(w1, w2), w5 = cmulf(w1, w4);
                float2 w6 = cmulf(w2, w4), w7 = cmulf(w3, w4);
                v[1] = cmulf(v[1], w1); v[2] = cmulf(v[2], w2); v[3] = cmulf(v[3], w3);
                v[4] = cmulf(v[4], w4); v[5] = cmulf(v[5], w5); v[6] = cmulf(v[6], w6);
                v[7] = cmulf(v[7], w7);
            }
            fft8<false>(v);
            const int idxD = ((j - base) << 3) + base;
#pragma unroll
            for (int r = 0; r < 8; r++) dst[SWZ(idxD + r * Ns)] = v[r];
        }
        __syncthreads();
        float2* t = src; src = dst; dst = t;
    }
#pragma unroll
    for (int q = 0; q < 2; q++) {
        int j = jt + q * 256;
        float2 v[4];
#pragma unroll
        for (int r = 0; r < 4; r++) v[r] = src[SWZ(j + r * 512)];
        float4 T1 = g_twd[1024 + j];
        float4 T2 = g_twd[512 + j];
        float2 w1 = make_float2(T1.x, -T1.y);
        float2 w2 = make_float2(T2.x, -T2.y);
        float2 w3 = cmulf(w1, w2);
        v[1] = cmulf(v[1], w1); v[2] = cmulf(v[2], w2); v[3] = cmulf(v[3], w3);
        fft4<false>(v);
#pragma unroll
        for (int r = 0; r < 4; r++) dst[SWZ(j + r * 512)] = v[r];
    }
    __syncthreads();
}

// ---------------------------------------------------------------------------
// fused khat-pair + t1 (unchanged from R13)
// ---------------------------------------------------------------------------
__global__ void __launch_bounds__(512, 2) khat_t1_kernel(
    const float* __restrict__ pr, const float* __restrict__ qr,
    const float* __restrict__ lamr, const float* __restrict__ Br,
    const float* __restrict__ Ctr, const float* __restrict__ logstep,
    const float* __restrict__ u) {
    extern __shared__ float2 sm[];
    int tid = threadIdx.x;

    __shared__ float2 t1tile[2][32][33];        // t1 blocks only

    if (blockIdx.x >= NPAIR) {
        int fb   = blockIdx.x - NPAIR;
        int half = tid >> 8;
        int tid2 = tid & 255;
        int tileId = fb * 2 + half;
        int pt = (tileId & 7) * 32;
        int rt = (tileId >> 3) * 32;
        int tx = tid2 & 31, ty = tid2 >> 5;
        const float2* uf2 = reinterpret_cast<const float2*>(u);
#pragma unroll
        for (int i = 0; i < 4; i++) {
            int row = ty + i * 8;
            t1tile[half][row][tx] = uf2[(size_t)(rt + row) * NPAIR + pt + tx];
        }
        __syncthreads();
        int b = rt >> 11, l0 = rt & (LSEQ - 1);
#pragma unroll
        for (int i = 0; i < 4; i++) {
            int p = pt + ty + i * 8;
            g_ut[((size_t)(b * NPAIR + p)) * LSEQ + l0 + tx] = t1tile[half][tx][ty + i * 8];
        }
        return;
    }

    float2* buf0 = sm;
    float2* buf1 = sm + LFFT;

    __shared__ float2 w00[2][NSTATE], w01[2][NSTATE], w10[2][NSTATE], w11[2][NSTATE];
    __shared__ float2 lams[NSTATE];
    __shared__ float s_inv2step[2];

    int pidx = blockIdx.x;
    int d0 = pidx * 2;

    if (tid < 2 * NSTATE) {
        int ch = tid >> 6, n = tid & (NSTATE - 1);
        int d = d0 + ch;
        float2 p  = make_float2(pr[2*n],  pr[2*n+1]);
        float2 qc = make_float2(qr[2*n], -qr[2*n+1]);
        float2 Bv = make_float2(Br[(d*NSTATE+n)*2],  Br[(d*NSTATE+n)*2+1]);
        float2 Cc = make_float2(Ctr[(d*NSTATE+n)*2], -Ctr[(d*NSTATE+n)*2+1]);
        w00[ch][n] = cmulf(Cc, Bv);
        w01[ch][n] = cmulf(Cc, p);
        w10[ch][n] = cmulf(qc, Bv);
        w11[ch][n] = cmulf(qc, p);
        if (ch == 0) lams[n] = make_float2(lamr[2*n], lamr[2*n+1]);
    }
    if (tid < 2) s_inv2step[tid] = 2.0f * expf(-logstep[d0 + tid]);
    __syncthreads();

    float ts[4];
#pragma unroll
    for (int kk = 0; kk < 4; kk++) {
        int l = tid + kk * 512;
        ts[kk] = tanf((PI_F / (float)LSEQ) * (float)l);
    }

    for (int ch = 0; ch < 2; ch++) {
        float inv2step = s_inv2step[ch];
        ull Gp[2];
        Gp[0] = pk(-inv2step * ts[0], -inv2step * ts[1]);
        Gp[1] = pk(-inv2step * ts[2], -inv2step * ts[3]);

        ull a00x[2] = {0, 0}, a00y[2] = {0, 0};
        ull a01x[2] = {0, 0}, a01y[2] = {0, 0};
        ull a10x[2] = {0, 0}, a10y[2] = {0, 0};
        ull a11x[2] = {0, 0}, a11y[2] = {0, 0};
        const ull NEG1 = 0xBF800000BF800000ULL;

        for (int n = 0; n < NSTATE; n++) {
            float2 lw  = lams[n];
            float2 v00 = w00[ch][n], v01 = w01[ch][n];
            float2 v10 = w10[ch][n], v11 = w11[ch][n];
            float dr = -lw.x;
            ull nlwy = pk(-lw.y, -lw.y);
            ull drp  = pk(dr, dr);
            ull drsq = pk(dr * dr, dr * dr);
            ull x00 = pk(v00.x, v00.x), y00 = pk(v00.y, v00.y);
            ull x01 = pk(v01.x, v01.x), y01 = pk(v01.y, v01.y);
            ull x10 = pk(v10.x, v10.x), y10 = pk(v10.y, v10.y);
            ull x11 = pk(v11.x, v11.x), y11 = pk(v11.y, v11.y);
#pragma unroll
            for (int j = 0; j < 2; j++) {
                ull dip = padd(Gp[j], nlwy);
                ull mag = pfma(dip, dip, drsq);
                float m0, m1;
                upk(mag, m0, m1);
                ull invp = pk(frcpa(m0), frcpa(m1));
                ull sx  = pmul(drp, invp);
                ull ty  = pmul(dip, invp);
                ull nty = pmul(ty, NEG1);
                a00x[j] = pfma(x00, sx, a00x[j]); a00x[j] = pfma(y00, ty,  a00x[j]);
                a00y[j] = pfma(y00, sx, a00y[j]); a00y[j] = pfma(x00, nty, a00y[j]);
                a01x[j] = pfma(x01, sx, a01x[j]); a01x[j] = pfma(y01, ty,  a01x[j]);
                a01y[j] = pfma(y01, sx, a01y[j]); a01y[j] = pfma(x01, nty, a01y[j]);
                a10x[j] = pfma(x10, sx, a10x[j]); a10x[j] = pfma(y10, ty,  a10x[j]);
                a10y[j] = pfma(y10, sx, a10y[j]); a10y[j] = pfma(x10, nty, a10y[j]);
                a11x[j] = pfma(x11, sx, a11x[j]); a11x[j] = pfma(y11, ty,  a11x[j]);
                a11y[j] = pfma(y11, sx, a11y[j]); a11y[j] = pfma(x11, nty, a11y[j]);
            }
        }

        float2* dstb = buf0 + ch * 2048;
#pragma unroll
        for (int j = 0; j < 2; j++) {
            float x0, x1, y0, y1;
            float2 A00[2], A01[2], A10[2], A11[2];
            upk(a00x[j], x0, x1); upk(a00y[j], y0, y1);
            A00[0] = make_float2(x0, y0); A00[1] = make_float2(x1, y1);
            upk(a01x[j], x0, x1); upk(a01y[j], y0, y1);
            A01[0] = make_float2(x0, y0); A01[1] = make_float2(x1, y1);
            upk(a10x[j], x0, x1); upk(a10y[j], y0, y1);
            A10[0] = make_float2(x0, y0); A10[1] = make_float2(x1, y1);
            upk(a11x[j], x0, x1); upk(a11y[j], y0, y1);
            A11[0] = make_float2(x0, y0); A11[1] = make_float2(x1, y1);
#pragma unroll
            for (int slot = 0; slot < 2; slot++) {
                int kk = 2 * j + slot;
                int l = tid + kk * 512;
                float2 den = make_float2(1.0f + A11[slot].x, A11[slot].y);
                float dinv = __fdividef(1.0f, den.x * den.x + den.y * den.y);
                float2 num = cmulf(A01[slot], A10[slot]);
                float2 frac = make_float2((num.x * den.x + num.y * den.y) * dinv,
                                          (num.y * den.x - num.x * den.y) * dinv);
                float2 inner = make_float2(A00[slot].x - frac.x, A00[slot].y - frac.y);
                float2 c = make_float2(1.0f, -ts[kk]);
                dstb[SWZ(l)] = cmulf(c, inner);
            }
        }
    }
    __syncthreads();

    ifft2048_dual(buf0, buf1, tid);

    // fused: K-pair extraction + fft4096 stage 0 (top half zero), buf0 -> buf1
    const float invL = 1.0f / (float)LSEQ;
    {
        float2 a[4], v[8];
#pragma unroll
        for (int r = 0; r < 4; r++) {
            int m = tid + 512 * r;
            int rm = (LSEQ - m) & (LSEQ - 1);
            a[r] = make_float2(buf0[SWZ(rm)].x * invL,
                               buf0[2048 + SWZ(rm)].x * invL);
        }
        fft8_z4(a, v);
        int idxD = tid << 3;
#pragma unroll
        for (int r = 0; r < 8; r++) buf1[SWZ(idxD + r)] = v[r];
    }
    __syncthreads();

    // fft4096 stages 1..3 (Ns = 8, 64, 512)
    float2* srcb = buf1;
    float2* dstb2 = buf0;
#pragma unroll
    for (int s = 1; s < 4; s++) {
        const int Ns = 1 << (3 * s);
        int j = tid;
        float2 v[8];
#pragma unroll
        for (int r = 0; r < 8; r++) v[r] = srcb[SWZ(j + r * 512)];
        const int base = j & (Ns - 1);
        {
            float4 T1 = g_twd[4 * Ns + base];
            float4 T2 = g_twd[2 * Ns + base];
            float4 T4 = g_twd[Ns + base];
            float2 w1 = make_float2(T1.x, T1.y);
            float2 w2 = make_float2(T2.x, T2.y);
            float2 w4 = make_float2(T4.x, T4.y);
            float2 w3 = cmulf(w1, w2), w5 = cmulf(w1, w4);
            float2 w6 = cmulf(w2, w4), w7 = cmulf(w3, w4);
            v[1] = cmulf(v[1], w1); v[2] = cmulf(v[2], w2); v[3] = cmulf(v[3], w3);
            v[4] = cmulf(v[4], w4); v[5] = cmulf(v[5], w5); v[6] = cmulf(v[6], w6);
            v[7] = cmulf(v[7], w7);
        }
        fft8<true>(v);
        const int idxD = ((j - base) << 3) + base;
#pragma unroll
        for (int r = 0; r < 8; r++) dstb2[SWZ(idxD + r * Ns)] = v[r];
        __syncthreads();
        float2* tmp = srcb; srcb = dstb2; dstb2 = tmp;
    }
    float2* resZ = srcb;   // buf0 after 3 swaps

    const float invF = 0.5f / (float)LFFT;
    float4* KP4 = g_KPM4 + (size_t)pidx * LFFT;
    for (int k = tid; k < LFFT; k += 512) {
        float2 Z  = resZ[SWZ(k)];
        float2 Zm = resZ[SWZ((LFFT - k) & (LFFT - 1))];
        float2 h0 = make_float2(0.5f * (Z.x + Zm.x), 0.5f * (Z.y - Zm.y));
        float2 dv = make_float2(Z.x - Zm.x, Z.y + Zm.y);
        float2 h1 = make_float2(0.5f * dv.y, -0.5f * dv.x);
        KP4[k] = make_float4((h0.x + h1.x) * invF, (h0.y + h1.y) * invF,
                             (h0.x - h1.x) * invF, (h0.y - h1.y) * invF);
    }
}

// ---------------------------------------------------------------------------
// conv: radix-16, PING-PONG smem (64KB), 5 barriers instead of 9
// ---------------------------------------------------------------------------
__global__ void __launch_bounds__(256, 3) conv_kernel(const float* __restrict__ Dvec) {
    extern __shared__ float2 s[];   // 2 x 4096 float2 = 64KB
    float2* A = s;
    float2* B = s + LFFT;

    int t    = threadIdx.x;
    int blk  = blockIdx.x;
    int pair = blk & (NPAIR - 1);
    int b    = blk >> 8;
    int d0   = pair * 2;

    const float2* ut = g_ut + ((size_t)(b * NPAIR + pair)) * LSEQ;
    float2*       yt = g_yt + ((size_t)(b * NPAIR + pair)) * LSEQ;

    // load + forward stage 0 (zero-padded) -> A
    {
        float2 x[8], v[16];
#pragma unroll
        for (int r = 0; r < 8; r++) x[r] = ut[t + 256 * r];
        fft16_z8(x, v);
#pragma unroll
        for (int r = 0; r < 16; r++) A[SW16(16 * t + r)] = v[r];
        __syncthreads();
    }

    stage16_pp<16,  false>(A, B, t);      // A -> B
    stage16_pp<256, false>(B, A, t);      // B -> A

    pw_inv0_pp(A, B, t, g_KPM4 + (size_t)pair * LFFT);   // A -> B

    stage16_pp<16, true>(B, A, t);        // B -> A

    // final inverse stage (Ns=256), reads A, outputs 0..7 to global
    {
        float2 v[16];
#pragma unroll
        for (int r = 0; r < 16; r++) v[r] = A[SW16(t + 256 * r)];
        twapply16<true>(v, g_twd[2048 + t], g_twd[1024 + t],
                           g_twd[512 + t],  g_twd[256 + t]);
        float2 o[8];
        fft16_lo8(v, o);

        float D0 = Dvec[d0], D1 = Dvec[d0 + 1];
#pragma unroll
        for (int r = 0; r < 8; r++) {
            float2 uv = ut[t + 256 * r];
            yt[t + 256 * r] = make_float2(o[r].x + D0 * uv.x, o[r].y + D1 * uv.y);
        }
    }
}

// ---------------------------------------------------------------------------
// Inputs: u, p_ri, q_ri, lam_ri, B_ri, Ct_ri, D, log_step
// pad puts conv at ncu launch index 3 this round.
// ---------------------------------------------------------------------------
extern "C" void kernel_launch(void* const* d_in, const int* in_sizes, int n_in,
                              void* d_out, int out_size) {
    const float* u   = (const float*)d_in[0];
    const float* pr  = (const float*)d_in[1];
    const float* qr  = (const float*)d_in[2];
    const float* lam = (const float*)d_in[3];
    const float* Br  = (const float*)d_in[4];
    const float* Ct  = (const float*)d_in[5];
    const float* Dv  = (const float*)d_in[6];
    const float* ls  = (const float*)d_in[7];
    float* out = (float*)d_out;

    const int smem_khat = 2 * LFFT * (int)sizeof(float2);   // 64 KB
    const int smem_conv = 2 * LFFT * (int)sizeof(float2);   // 64 KB ping-pong
    cudaFuncSetAttribute(khat_t1_kernel, cudaFuncAttributeMaxDynamicSharedMemorySize, smem_khat);
    cudaFuncSetAttribute(conv_kernel,   cudaFuncAttributeMaxDynamicSharedMemorySize, smem_conv);

    init_twd_kernel<<<LFFT / 512, 512>>>();                                            // 0
    khat_t1_kernel<<<NPAIR + 4096, 512, smem_khat>>>(pr, qr, lam, Br, Ct, ls, u);      // 1
    pad_kernel<<<1, 32>>>();                                                            // 2
    conv_kernel<<<NBATCH * NPAIR, 256, smem_conv>>>(Dv);                                // 3  <- ncu target
    t2_kernel<<<dim3(NPAIR / 32, NBATCH * LSEQ / 32), 256>>>(out);                      // 4
}

// round 15
// speedup vs baseline: 1.0232x; 1.0232x over previous
#include <cuda_runtime.h>
#include <math.h>

#define LSEQ   2048
#define LFFT   4096
#define DMODEL 512
#define NSTATE 64
#define NBATCH 16
#define NPAIR  (DMODEL / 2)
#define PI_F   3.14159265358979323846f

#define SWZ(i)  ((i) ^ (((i) >> 3) & 15))   // float2 swizzle (khat)
#define SW16(e) ((e) ^ (((e) >> 4) & 15))   // float2 swizzle (conv radix-16)

typedef unsigned long long ull;

__device__ float4 g_KPM4[NPAIR * LFFT];             // per pair, per bin: (P.re,P.im,M.re,M.im)
__device__ float4 g_twd[LFFT];                      // (c,s,-s,c): e^{-i pi base/Ns}
__device__ float2 g_ut[NBATCH * NPAIR * LSEQ];      // transposed input
__device__ float2 g_yt[NBATCH * NPAIR * LSEQ];      // transposed output

// ---------------- packed f32x2 helpers ----------------
__device__ __forceinline__ ull pk(float x, float y) {
    ull r; asm("mov.b64 %0, {%1,%2};" : "=l"(r) : "f"(x), "f"(y)); return r;
}
__device__ __forceinline__ void upk(ull v, float& x, float& y) {
    asm("mov.b64 {%0,%1}, %2;" : "=f"(x), "=f"(y) : "l"(v));
}
__device__ __forceinline__ ull padd(ull a, ull b) {
    ull r; asm("add.rn.f32x2 %0, %1, %2;" : "=l"(r) : "l"(a), "l"(b)); return r;
}
__device__ __forceinline__ ull pmul(ull a, ull b) {
    ull r; asm("mul.rn.f32x2 %0, %1, %2;" : "=l"(r) : "l"(a), "l"(b)); return r;
}
__device__ __forceinline__ ull pfma(ull a, ull b, ull c) {
    ull r; asm("fma.rn.f32x2 %0, %1, %2, %3;" : "=l"(r) : "l"(a), "l"(b), "l"(c)); return r;
}
__device__ __forceinline__ float frcpa(float x) {
    float r; asm("rcp.approx.f32 %0, %1;" : "=f"(r) : "f"(x)); return r;
}

__device__ __forceinline__ float2 cmulf(float2 a, float2 b) {
    return make_float2(a.x * b.x - a.y * b.y, a.x * b.y + a.y * b.x);
}
__device__ __forceinline__ float2 cadd(float2 a, float2 b) {
    union { float2 f; ull u; } A, B, R;
    A.f = a; B.f = b;
    asm("add.rn.f32x2 %0, %1, %2;" : "=l"(R.u) : "l"(A.u), "l"(B.u));
    return R.f;
}
__device__ __forceinline__ float2 csub(float2 a, float2 b) {
    union { float2 f; ull u; } A, B, R;
    A.f = a; B.f = b;
    asm("fma.rn.f32x2 %0, %1, %2, %3;"
        : "=l"(R.u) : "l"(B.u), "l"(0xBF800000BF800000ULL), "l"(A.u));
    return R.f;
}
__device__ __forceinline__ float2 cmulF(float2 v, float2 wn, float2 wr) {
    return make_float2(v.x * wn.x + v.y * wr.x, v.x * wn.y + v.y * wr.y);
}

template<bool FWD> __device__ __forceinline__ float2 mul_j(float2 a) {
    return FWD ? make_float2(a.y, -a.x) : make_float2(-a.y, a.x);
}
template<bool FWD> __device__ __forceinline__ float2 mul_w1(float2 a) {
    const float C = 0.70710678118654752f;
    return FWD ? make_float2(C * (a.x + a.y), C * (a.y - a.x))
               : make_float2(C * (a.x - a.y), C * (a.x + a.y));
}
template<bool FWD> __device__ __forceinline__ float2 mul_w3(float2 a) {
    const float C = 0.70710678118654752f;
    return FWD ? make_float2(C * (a.y - a.x), -C * (a.x + a.y))
               : make_float2(-C * (a.x + a.y), C * (a.x - a.y));
}

template<bool FWD>
__device__ __forceinline__ void fft8(float2* v) {
    float2 t0 = cadd(v[0], v[4]), t4 = csub(v[0], v[4]);
    float2 t1 = cadd(v[1], v[5]), t5 = mul_w1<FWD>(csub(v[1], v[5]));
    float2 t2 = cadd(v[2], v[6]), t6 = mul_j<FWD>(csub(v[2], v[6]));
    float2 t3 = cadd(v[3], v[7]), t7 = mul_w3<FWD>(csub(v[3], v[7]));
    float2 u0 = cadd(t0, t2), u2 = csub(t0, t2);
    float2 u1 = cadd(t1, t3), u3 = mul_j<FWD>(csub(t1, t3));
    float2 u4 = cadd(t4, t6), u6 = csub(t4, t6);
    float2 u5 = cadd(t5, t7), u7 = mul_j<FWD>(csub(t5, t7));
    v[0] = cadd(u0, u1); v[4] = csub(u0, u1);
    v[2] = cadd(u2, u3); v[6] = csub(u2, u3);
    v[1] = cadd(u4, u5); v[5] = csub(u4, u5);
    v[3] = cadd(u6, u7); v[7] = csub(u6, u7);
}

// forward fft8, inputs 4..7 == 0
__device__ __forceinline__ void fft8_z4(const float2* a, float2* v) {
    float2 t0 = a[0], t4 = a[0];
    float2 t1 = a[1], t5 = mul_w1<true>(a[1]);
    float2 t2 = a[2], t6 = mul_j<true>(a[2]);
    float2 t3 = a[3], t7 = mul_w3<true>(a[3]);
    float2 u0 = cadd(t0, t2), u2 = csub(t0, t2);
    float2 u1 = cadd(t1, t3), u3 = mul_j<true>(csub(t1, t3));
    float2 u4 = cadd(t4, t6), u6 = csub(t4, t6);
    float2 u5 = cadd(t5, t7), u7 = mul_j<true>(csub(t5, t7));
    v[0] = cadd(u0, u1); v[4] = csub(u0, u1);
    v[2] = cadd(u2, u3); v[6] = csub(u2, u3);
    v[1] = cadd(u4, u5); v[5] = csub(u4, u5);
    v[3] = cadd(u6, u7); v[7] = csub(u6, u7);
}

template<bool FWD>
__device__ __forceinline__ void fft4(float2* v) {
    float2 t0 = cadd(v[0], v[2]), t2 = csub(v[0], v[2]);
    float2 t1 = cadd(v[1], v[3]), t3 = mul_j<FWD>(csub(v[1], v[3]));
    v[0] = cadd(t0, t1); v[2] = csub(t0, t1);
    v[1] = cadd(t2, t3); v[3] = csub(t2, t3);
}

// ---------------- radix-16 building blocks (conv) ----------------
#define C16 0.92387953251128675613f
#define S16 0.38268343236508977173f

template<bool FWD>
__device__ __forceinline__ void fft16_combine(float2* E, float2* O, float2* v) {
    O[1] = cmulf(O[1], make_float2( C16, FWD ? -S16 :  S16));
    O[2] = mul_w1<FWD>(O[2]);
    O[3] = cmulf(O[3], make_float2( S16, FWD ? -C16 :  C16));
    O[4] = mul_j<FWD>(O[4]);
    O[5] = cmulf(O[5], make_float2(-S16, FWD ? -C16 :  C16));
    O[6] = mul_w3<FWD>(O[6]);
    O[7] = cmulf(O[7], make_float2(-C16, FWD ? -S16 :  S16));
#pragma unroll
    for (int k = 0; k < 8; k++) {
        v[k]     = cadd(E[k], O[k]);
        v[k + 8] = csub(E[k], O[k]);
    }
}

template<bool FWD>
__device__ __forceinline__ void fft16(float2* v) {
    float2 E[8] = {v[0], v[2], v[4], v[6], v[8], v[10], v[12], v[14]};
    float2 O[8] = {v[1], v[3], v[5], v[7], v[9], v[11], v[13], v[15]};
    fft8<FWD>(E); fft8<FWD>(O);
    fft16_combine<FWD>(E, O, v);
}

__device__ __forceinline__ void fft16_z8(const float2* x, float2* v) {
    float2 ein[4] = {x[0], x[2], x[4], x[6]};
    float2 oin[4] = {x[1], x[3], x[5], x[7]};
    float2 E[8], O[8];
    fft8_z4(ein, E);
    fft8_z4(oin, O);
    fft16_combine<true>(E, O, v);
}

__device__ __forceinline__ void fft16_lo8(float2* v, float2* o) {
    float2 E[8] = {v[0], v[2], v[4], v[6], v[8], v[10], v[12], v[14]};
    float2 O[8] = {v[1], v[3], v[5], v[7], v[9], v[11], v[13], v[15]};
    fft8<false>(E); fft8<false>(O);
    O[1] = cmulf(O[1], make_float2( C16,  S16));
    O[2] = mul_w1<false>(O[2]);
    O[3] = cmulf(O[3], make_float2( S16,  C16));
    O[4] = mul_j<false>(O[4]);
    O[5] = cmulf(O[5], make_float2(-S16,  C16));
    O[6] = mul_w3<false>(O[6]);
    O[7] = cmulf(O[7], make_float2(-C16,  S16));
#pragma unroll
    for (int k = 0; k < 8; k++) o[k] = cadd(E[k], O[k]);
}

template<bool INV>
__device__ __forceinline__ void twapply16(float2* v, float4 W1, float4 W2, float4 W4, float4 W8) {
    float2 w1n, w1r, w2n, w2r, w4n, w4r, w8n, w8r;
    if (!INV) {
        w1n = make_float2(W1.x, W1.y); w1r = make_float2(W1.z, W1.w);
        w2n = make_float2(W2.x, W2.y); w2r = make_float2(W2.z, W2.w);
        w4n = make_float2(W4.x, W4.y); w4r = make_float2(W4.z, W4.w);
        w8n = make_float2(W8.x, W8.y); w8r = make_float2(W8.z, W8.w);
    } else {
        w1n = make_float2(W1.x, -W1.y); w1r = make_float2(-W1.z, W1.w);
        w2n = make_float2(W2.x, -W2.y); w2r = make_float2(-W2.z, W2.w);
        w4n = make_float2(W4.x, -W4.y); w4r = make_float2(-W4.z, W4.w);
        w8n = make_float2(W8.x, -W8.y); w8r = make_float2(-W8.z, W8.w);
    }
    v[1] = cmulF(v[1], w1n, w1r);
    v[2] = cmulF(v[2], w2n, w2r);
    v[4] = cmulF(v[4], w4n, w4r);
    v[8] = cmulF(v[8], w8n, w8r);
    float2 w3n = cmulF(w2n, w1n, w1r), w3r = make_float2(-w3n.y, w3n.x);
    v[3] = cmulF(v[3], w3n, w3r);
    float2 w5n = cmulF(w4n, w1n, w1r), w5r = make_float2(-w5n.y, w5n.x);
    v[5] = cmulF(v[5], w5n, w5r);
    float2 w6n = cmulF(w4n, w2n, w2r), w6r = make_float2(-w6n.y, w6n.x);
    v[6] = cmulF(v[6], w6n, w6r);
    float2 w7n = cmulF(w4n, w3n, w3r), w7r = make_float2(-w7n.y, w7n.x);
    v[7] = cmulF(v[7], w7n, w7r);
    float2 w9n  = cmulF(w8n, w1n, w1r), w9r  = make_float2(-w9n.y,  w9n.x);
    v[9]  = cmulF(v[9],  w9n,  w9r);
    float2 w10n = cmulF(w8n, w2n, w2r), w10r = make_float2(-w10n.y, w10n.x);
    v[10] = cmulF(v[10], w10n, w10r);
    float2 w11n = cmulF(w8n, w3n, w3r), w11r = make_float2(-w11n.y, w11n.x);
    v[11] = cmulF(v[11], w11n, w11r);
    float2 w12n = cmulF(w8n, w4n, w4r), w12r = make_float2(-w12n.y, w12n.x);
    v[12] = cmulF(v[12], w12n, w12r);
    float2 w13n = cmulF(w8n, w5n, w5r), w13r = make_float2(-w13n.y, w13n.x);
    v[13] = cmulF(v[13], w13n, w13r);
    float2 w14n = cmulF(w8n, w6n, w6r), w14r = make_float2(-w14n.y, w14n.x);
    v[14] = cmulF(v[14], w14n, w14r);
    float2 w15n = cmulF(w8n, w7n, w7r), w15r = make_float2(-w15n.y, w15n.x);
    v[15] = cmulF(v[15], w15n, w15r);
}

template<int NS, bool INV>
__device__ __forceinline__ void stage16_ip(float2* s, int t) {
    float2 v[16];
#pragma unroll
    for (int r = 0; r < 16; r++) v[r] = s[SW16(t + 256 * r)];
    const int base = t & (NS - 1);
    twapply16<INV>(v, g_twd[8 * NS + base], g_twd[4 * NS + base],
                      g_twd[2 * NS + base], g_twd[NS + base]);
    fft16<!INV>(v);
    __syncthreads();
    const int idxD = ((t - base) << 4) + base;
#pragma unroll
    for (int r = 0; r < 16; r++) s[SW16(idxD + NS * r)] = v[r];
    __syncthreads();
}

// pointwise with P/M: Y = z*P + conj(zm)*M
__device__ __forceinline__ float2 pwone_pm(float2 z, float2 zm, float2 P, float2 M) {
    return make_float2(z.x * P.x - z.y * P.y + zm.x * M.x + zm.y * M.y,
                       z.x * P.y + z.y * P.x + zm.x * M.y - zm.y * M.x);
}

__device__ __forceinline__ void inv_stage0_pw16(float2* s, int t, const float4* Kp) {
    float2 v[16];
#pragma unroll
    for (int r = 0; r < 16; r++) {
        int e = t + 256 * r;
        float2 z  = s[SW16(e)];
        float2 zm = s[SW16((LFFT - e) & (LFFT - 1))];   // e=0 -> itself
        float4 K4 = Kp[e];
        v[r] = pwone_pm(z, zm, make_float2(K4.x, K4.y), make_float2(K4.z, K4.w));
    }
    fft16<false>(v);
    __syncthreads();
#pragma unroll
    for (int r = 0; r < 16; r++) s[SW16(16 * t + r)] = v[r];
    __syncthreads();
}

__global__ void init_twd_kernel() {
    int i = blockIdx.x * blockDim.x + threadIdx.x;
    if (i >= LFFT) return;
    if (i == 0) { g_twd[0] = make_float4(1.0f, 0.0f, 0.0f, 1.0f); return; }
    int k = 31 - __clz(i);
    int Ns = 1 << k;
    int base = i - Ns;
    float ang = -PI_F * (float)base / (float)Ns;
    float s, c;
    sincosf(ang, &s, &c);
    g_twd[i] = make_float4(c, s, -s, c);
}

// ---------------- t2 (output transpose) ----------------
__global__ void __launch_bounds__(256) t2_kernel(float* __restrict__ out) {
    __shared__ float2 tile[32][33];
    int pt = blockIdx.x * 32;
    int rt = blockIdx.y * 32;
    int tx = threadIdx.x & 31, ty = threadIdx.x >> 5;
    int b = rt >> 11, l0 = rt & (LSEQ - 1);
#pragma unroll
    for (int i = 0; i < 4; i++) {
        int p = pt + ty + i * 8;
        tile[ty + i * 8][tx] = g_yt[((size_t)(b * NPAIR + p)) * LSEQ + l0 + tx];
    }
    __syncthreads();
    float2* of2 = reinterpret_cast<float2*>(out);
#pragma unroll
    for (int i = 0; i < 4; i++) {
        int row = ty + i * 8;
        of2[(size_t)(rt + row) * NPAIR + pt + tx] = tile[tx][row];
    }
}

// dual-channel inverse FFT2048
__device__ void ifft2048_dual(float2* b0, float2* b1, int tid) {
    int ch = tid >> 8;
    int jt = tid & 255;
    float2* src = b0 + ch * 2048;
    float2* dst = b1 + ch * 2048;
#pragma unroll
    for (int s = 0; s < 3; s++) {
        const int Ns = 1 << (3 * s);
        {
            int j = jt;
            float2 v[8];
#pragma unroll
            for (int r = 0; r < 8; r++) v[r] = src[SWZ(j + r * 256)];
            const int base = j & (Ns - 1);
            if (Ns > 1) {
                float4 T1 = g_twd[4 * Ns + base];
                float4 T2 = g_twd[2 * Ns + base];
                float4 T4 = g_twd[Ns + base];
                float2 w1 = make_float2(T1.x, -T1.y);
                float2 w2 = make_float2(T2.x, -T2.y);
                float2 w4 = make_float2(T4.x, -T4.y);
                float2 w3 = cmulf(w1, w2), w5 = cmulf(w1, w4);
                float2 w6 = cmulf(w2, w4), w7 = cmulf(w3, w4);
                v[1] = cmulf(v[1], w1); v[2] = cmulf(v[2], w2); v[3] = cmulf(v[3], w3);
                v[4] = cmulf(v[4], w4); v[5] = cmulf(v[5], w5); v[6] = cmulf(v[6], w6);
                v[7] = cmulf(v[7], w7);
            }
            fft8<false>(v);
            const int idxD = ((j - base) << 3) + base;
#pragma unroll
            for (int r = 0; r < 8; r++) dst[SWZ(idxD + r * Ns)] = v[r];
        }
        __syncthreads();
        float2* t = src; src = dst; dst = t;
    }
#pragma unroll
    for (int q = 0; q < 2; q++) {
        int j = jt + q * 256;
        float2 v[4];
#pragma unroll
        for (int r = 0; r < 4; r++) v[r] = src[SWZ(j + r * 512)];
        float4 T1 = g_twd[1024 + j];
        float4 T2 = g_twd[512 + j];
        float2 w1 = make_float2(T1.x, -T1.y);
        float2 w2 = make_float2(T2.x, -T2.y);
        float2 w3 = cmulf(w1, w2);
        v[1] = cmulf(v[1], w1); v[2] = cmulf(v[2], w2); v[3] = cmulf(v[3], w3);
        fft4<false>(v);
#pragma unroll
        for (int r = 0; r < 4; r++) dst[SWZ(j + r * 512)] = v[r];
    }
    __syncthreads();
}

// P/M split for one (Z, Zm) pair -> float4 for bin k
__device__ __forceinline__ float4 pm_pack(float2 Z, float2 Zm, float invF) {
    float2 h0 = make_float2(0.5f * (Z.x + Zm.x), 0.5f * (Z.y - Zm.y));
    float2 dv = make_float2(Z.x - Zm.x, Z.y + Zm.y);
    float2 h1 = make_float2(0.5f * dv.y, -0.5f * dv.x);
    return make_float4((h0.x + h1.x) * invF, (h0.y + h1.y) * invF,
                       (h0.x - h1.x) * invF, (h0.y - h1.y) * invF);
}

// ---------------------------------------------------------------------------
// fused khat-pair + t1 (R13 structure; half-range P/M epilogue)
// ---------------------------------------------------------------------------
__global__ void __launch_bounds__(512, 2) khat_t1_kernel(
    const float* __restrict__ pr, const float* __restrict__ qr,
    const float* __restrict__ lamr, const float* __restrict__ Br,
    const float* __restrict__ Ctr, const float* __restrict__ logstep,
    const float* __restrict__ u) {
    extern __shared__ float2 sm[];
    int tid = threadIdx.x;

    __shared__ float2 t1tile[2][32][33];        // t1 blocks only

    if (blockIdx.x >= NPAIR) {
        int fb   = blockIdx.x - NPAIR;
        int half = tid >> 8;
        int tid2 = tid & 255;
        int tileId = fb * 2 + half;
        int pt = (tileId & 7) * 32;
        int rt = (tileId >> 3) * 32;
        int tx = tid2 & 31, ty = tid2 >> 5;
        const float2* uf2 = reinterpret_cast<const float2*>(u);
#pragma unroll
        for (int i = 0; i < 4; i++) {
            int row = ty + i * 8;
            t1tile[half][row][tx] = uf2[(size_t)(rt + row) * NPAIR + pt + tx];
        }
        __syncthreads();
        int b = rt >> 11, l0 = rt & (LSEQ - 1);
#pragma unroll
        for (int i = 0; i < 4; i++) {
            int p = pt + ty + i * 8;
            g_ut[((size_t)(b * NPAIR + p)) * LSEQ + l0 + tx] = t1tile[half][tx][ty + i * 8];
        }
        return;
    }

    float2* buf0 = sm;
    float2* buf1 = sm + LFFT;

    __shared__ float2 w00[2][NSTATE], w01[2][NSTATE], w10[2][NSTATE], w11[2][NSTATE];
    __shared__ float2 lams[NSTATE];
    __shared__ float s_inv2step[2];

    int pidx = blockIdx.x;
    int d0 = pidx * 2;

    if (tid < 2 * NSTATE) {
        int ch = tid >> 6, n = tid & (NSTATE - 1);
        int d = d0 + ch;
        float2 p  = make_float2(pr[2*n],  pr[2*n+1]);
        float2 qc = make_float2(qr[2*n], -qr[2*n+1]);
        float2 Bv = make_float2(Br[(d*NSTATE+n)*2],  Br[(d*NSTATE+n)*2+1]);
        float2 Cc = make_float2(Ctr[(d*NSTATE+n)*2], -Ctr[(d*NSTATE+n)*2+1]);
        w00[ch][n] = cmulf(Cc, Bv);
        w01[ch][n] = cmulf(Cc, p);
        w10[ch][n] = cmulf(qc, Bv);
        w11[ch][n] = cmulf(qc, p);
        if (ch == 0) lams[n] = make_float2(lamr[2*n], lamr[2*n+1]);
    }
    if (tid < 2) s_inv2step[tid] = 2.0f * expf(-logstep[d0 + tid]);
    __syncthreads();

    float ts[4];
#pragma unroll
    for (int kk = 0; kk < 4; kk++) {
        int l = tid + kk * 512;
        ts[kk] = tanf((PI_F / (float)LSEQ) * (float)l);
    }

    for (int ch = 0; ch < 2; ch++) {
        float inv2step = s_inv2step[ch];
        ull Gp[2];
        Gp[0] = pk(-inv2step * ts[0], -inv2step * ts[1]);
        Gp[1] = pk(-inv2step * ts[2], -inv2step * ts[3]);

        ull a00x[2] = {0, 0}, a00y[2] = {0, 0};
        ull a01x[2] = {0, 0}, a01y[2] = {0, 0};
        ull a10x[2] = {0, 0}, a10y[2] = {0, 0};
        ull a11x[2] = {0, 0}, a11y[2] = {0, 0};
        const ull NEG1 = 0xBF800000BF800000ULL;

        for (int n = 0; n < NSTATE; n++) {
            float2 lw  = lams[n];
            float2 v00 = w00[ch][n], v01 = w01[ch][n];
            float2 v10 = w10[ch][n], v11 = w11[ch][n];
            float dr = -lw.x;
            ull nlwy = pk(-lw.y, -lw.y);
            ull drp  = pk(dr, dr);
            ull drsq = pk(dr * dr, dr * dr);
            ull x00 = pk(v00.x, v00.x), y00 = pk(v00.y, v00.y);
            ull x01 = pk(v01.x, v01.x), y01 = pk(v01.y, v01.y);
            ull x10 = pk(v10.x, v10.x), y10 = pk(v10.y, v10.y);
            ull x11 = pk(v11.x, v11.x), y11 = pk(v11.y, v11.y);
#pragma unroll
            for (int j = 0; j < 2; j++) {
                ull dip = padd(Gp[j], nlwy);
                ull mag = pfma(dip, dip, drsq);
                float m0, m1;
                upk(mag, m0, m1);
                ull invp = pk(frcpa(m0), frcpa(m1));
                ull sx  = pmul(drp, invp);
                ull ty  = pmul(dip, invp);
                ull nty = pmul(ty, NEG1);
                a00x[j] = pfma(x00, sx, a00x[j]); a00x[j] = pfma(y00, ty,  a00x[j]);
                a00y[j] = pfma(y00, sx, a00y[j]); a00y[j] = pfma(x00, nty, a00y[j]);
                a01x[j] = pfma(x01, sx, a01x[j]); a01x[j] = pfma(y01, ty,  a01x[j]);
                a01y[j] = pfma(y01, sx, a01y[j]); a01y[j] = pfma(x01, nty, a01y[j]);
                a10x[j] = pfma(x10, sx, a10x[j]); a10x[j] = pfma(y10, ty,  a10x[j]);
                a10y[j] = pfma(y10, sx, a10y[j]); a10y[j] = pfma(x10, nty, a10y[j]);
                a11x[j] = pfma(x11, sx, a11x[j]); a11x[j] = pfma(y11, ty,  a11x[j]);
                a11y[j] = pfma(y11, sx, a11y[j]); a11y[j] = pfma(x11, nty, a11y[j]);
            }
        }

        float2* dstb = buf0 + ch * 2048;
#pragma unroll
        for (int j = 0; j < 2; j++) {
            float x0, x1, y0, y1;
            float2 A00[2], A01[2], A10[2], A11[2];
            upk(a00x[j], x0, x1); upk(a00y[j], y0, y1);
            A00[0] = make_float2(x0, y0); A00[1] = make_float2(x1, y1);
            upk(a01x[j], x0, x1); upk(a01y[j], y0, y1);
            A01[0] = make_float2(x0, y0); A01[1] = make_float2(x1, y1);
            upk(a10x[j], x0, x1); upk(a10y[j], y0, y1);
            A10[0] = make_float2(x0, y0); A10[1] = make_float2(x1, y1);
            upk(a11x[j], x0, x1); upk(a11y[j], y0, y1);
            A11[0] = make_float2(x0, y0); A11[1] = make_float2(x1, y1);
#pragma unroll
            for (int slot = 0; slot < 2; slot++) {
                int kk = 2 * j + slot;
                int l = tid + kk * 512;
                float2 den = make_float2(1.0f + A11[slot].x, A11[slot].y);
                float dinv = __fdividef(1.0f, den.x * den.x + den.y * den.y);
                float2 num = cmulf(A01[slot], A10[slot]);
                float2 frac = make_float2((num.x * den.x + num.y * den.y) * dinv,
                                          (num.y * den.x - num.x * den.y) * dinv);
                float2 inner = make_float2(A00[slot].x - frac.x, A00[slot].y - frac.y);
                float2 c = make_float2(1.0f, -ts[kk]);
                dstb[SWZ(l)] = cmulf(c, inner);
            }
        }
    }
    __syncthreads();

    ifft2048_dual(buf0, buf1, tid);

    // fused: K-pair extraction + fft4096 stage 0 (top half zero), buf0 -> buf1
    const float invL = 1.0f / (float)LSEQ;
    {
        float2 a[4], v[8];
#pragma unroll
        for (int r = 0; r < 4; r++) {
            int m = tid + 512 * r;
            int rm = (LSEQ - m) & (LSEQ - 1);
            a[r] = make_float2(buf0[SWZ(rm)].x * invL,
                               buf0[2048 + SWZ(rm)].x * invL);
        }
        fft8_z4(a, v);
        int idxD = tid << 3;
#pragma unroll
        for (int r = 0; r < 8; r++) buf1[SWZ(idxD + r)] = v[r];
    }
    __syncthreads();

    // fft4096 stages 1..3 (Ns = 8, 64, 512)
    float2* srcb = buf1;
    float2* dstb2 = buf0;
#pragma unroll
    for (int s = 1; s < 4; s++) {
        const int Ns = 1 << (3 * s);
        int j = tid;
        float2 v[8];
#pragma unroll
        for (int r = 0; r < 8; r++) v[r] = srcb[SWZ(j + r * 512)];
        const int base = j & (Ns - 1);
        {
            float4 T1 = g_twd[4 * Ns + base];
            float4 T2 = g_twd[2 * Ns + base];
            float4 T4 = g_twd[Ns + base];
            float2 w1 = make_float2(T1.x, T1.y);
            float2 w2 = make_float2(T2.x, T2.y);
            float2 w4 = make_float2(T4.x, T4.y);
            float2 w3 = cmulf(w1, w2), w5 = cmulf(w1, w4);
            float2 w6 = cmulf(w2, w4), w7 = cmulf(w3, w4);
            v[1] = cmulf(v[1], w1); v[2] = cmulf(v[2], w2); v[3] = cmulf(v[3], w3);
            v[4] = cmulf(v[4], w4); v[5] = cmulf(v[5], w5); v[6] = cmulf(v[6], w6);
            v[7] = cmulf(v[7], w7);
        }
        fft8<true>(v);
        const int idxD = ((j - base) << 3) + base;
#pragma unroll
        for (int r = 0; r < 8; r++) dstb2[SWZ(idxD + r * Ns)] = v[r];
        __syncthreads();
        float2* tmp = srcb; srcb = dstb2; dstb2 = tmp;
    }
    float2* resZ = srcb;   // buf0 after 3 swaps

    // half-range P/M split: each (Z, Zm) pair read once, both bins written
    const float invF = 0.5f / (float)LFFT;
    float4* KP4 = g_KPM4 + (size_t)pidx * LFFT;
    for (int k = tid; k < 2048; k += 512) {
        float2 Z  = resZ[SWZ(k)];
        int km = (LFFT - k) & (LFFT - 1);   // k=0 -> 0
        float2 Zm = resZ[SWZ(km)];
        KP4[k] = pm_pack(Z, Zm, invF);
        if (k != 0) KP4[km] = pm_pack(Zm, Z, invF);
    }
    if (tid == 0) {
        float2 Z = resZ[SWZ(2048)];         // self-mirror bin
        KP4[2048] = pm_pack(Z, Z, invF);
    }
}

// ---------------------------------------------------------------------------
// conv: R13 in-place version (32KB smem, 3 CTAs/SM)
// ---------------------------------------------------------------------------
__global__ void __launch_bounds__(256, 3) conv_kernel(const float* __restrict__ Dvec) {
    extern __shared__ float2 s[];   // 4096 float2 = 32KB

    int t    = threadIdx.x;
    int blk  = blockIdx.x;
    int pair = blk & (NPAIR - 1);
    int b    = blk >> 8;
    int d0   = pair * 2;

    const float2* ut = g_ut + ((size_t)(b * NPAIR + pair)) * LSEQ;
    float2*       yt = g_yt + ((size_t)(b * NPAIR + pair)) * LSEQ;

    {
        float2 x[8], v[16];
#pragma unroll
        for (int r = 0; r < 8; r++) x[r] = ut[t + 256 * r];
        fft16_z8(x, v);
#pragma unroll
        for (int r = 0; r < 16; r++) s[SW16(16 * t + r)] = v[r];
        __syncthreads();
    }

    stage16_ip<16,  false>(s, t);
    stage16_ip<256, false>(s, t);

    inv_stage0_pw16(s, t, g_KPM4 + (size_t)pair * LFFT);

    stage16_ip<16, true>(s, t);

    {
        float2 v[16];
#pragma unroll
        for (int r = 0; r < 16; r++) v[r] = s[SW16(t + 256 * r)];
        twapply16<true>(v, g_twd[2048 + t], g_twd[1024 + t],
                           g_twd[512 + t],  g_twd[256 + t]);
        float2 o[8];
        fft16_lo8(v, o);

        float D0 = Dvec[d0], D1 = Dvec[d0 + 1];
#pragma unroll
        for (int r = 0; r < 8; r++) {
            float2 uv = ut[t + 256 * r];
            yt[t + 256 * r] = make_float2(o[r].x + D0 * uv.x, o[r].y + D1 * uv.y);
        }
    }
}

// ---------------------------------------------------------------------------
// Inputs: u, p_ri, q_ri, lam_ri, B_ri, Ct_ri, D, log_step
// ---------------------------------------------------------------------------
extern "C" void kernel_launch(void* const* d_in, const int* in_sizes, int n_in,
                              void* d_out, int out_size) {
    const float* u   = (const float*)d_in[0];
    const float* pr  = (const float*)d_in[1];
    const float* qr  = (const float*)d_in[2];
    const float* lam = (const float*)d_in[3];
    const float* Br  = (const float*)d_in[4];
    const float* Ct  = (const float*)d_in[5];
    const float* Dv  = (const float*)d_in[6];
    const float* ls  = (const float*)d_in[7];
    float* out = (float*)d_out;

    const int smem_khat = 2 * LFFT * (int)sizeof(float2);   // 64 KB
    const int smem_conv = LFFT * (int)sizeof(float2);       // 32 KB
    cudaFuncSetAttribute(khat_t1_kernel, cudaFuncAttributeMaxDynamicSharedMemorySize, smem_khat);
    cudaFuncSetAttribute(conv_kernel,   cudaFuncAttributeMaxDynamicSharedMemorySize, smem_conv);

    init_twd_kernel<<<LFFT / 512, 512>>>();                                            // 0
    khat_t1_kernel<<<NPAIR + 4096, 512, smem_khat>>>(pr, qr, lam, Br, Ct, ls, u);      // 1
    conv_kernel<<<NBATCH * NPAIR, 256, smem_conv>>>(Dv);                                // 2
    t2_kernel<<<dim3(NPAIR / 32, NBATCH * LSEQ / 32), 256>>>(out);                      // 3
}

// round 16
// speedup vs baseline: 1.0545x; 1.0306x over previous
#include <cuda_runtime.h>
#include <math.h>

#define LSEQ   2048
#define LFFT   4096
#define DMODEL 512
#define NSTATE 64
#define NBATCH 16
#define NPAIR  (DMODEL / 2)
#define PI_F   3.14159265358979323846f

#define SWZ(i)  ((i) ^ (((i) >> 3) & 15))   // float2 swizzle (khat)
#define SW16(e) ((e) ^ (((e) >> 4) & 15))   // float2 swizzle (conv radix-16)

typedef unsigned long long ull;

__device__ float4 g_KPM4[NPAIR * LFFT];             // per pair, per bin: (P.re,P.im,M.re,M.im)
__device__ float4 g_twd[LFFT];                      // (c,s,-s,c): e^{-i pi base/Ns} (khat only)
__device__ float2 g_ut[NBATCH * NPAIR * LSEQ];      // transposed input
__device__ float2 g_yt[NBATCH * NPAIR * LSEQ];      // transposed output

// ---------------- packed f32x2 helpers ----------------
__device__ __forceinline__ ull pk(float x, float y) {
    ull r; asm("mov.b64 %0, {%1,%2};" : "=l"(r) : "f"(x), "f"(y)); return r;
}
__device__ __forceinline__ void upk(ull v, float& x, float& y) {
    asm("mov.b64 {%0,%1}, %2;" : "=f"(x), "=f"(y) : "l"(v));
}
__device__ __forceinline__ ull padd(ull a, ull b) {
    ull r; asm("add.rn.f32x2 %0, %1, %2;" : "=l"(r) : "l"(a), "l"(b)); return r;
}
__device__ __forceinline__ ull pmul(ull a, ull b) {
    ull r; asm("mul.rn.f32x2 %0, %1, %2;" : "=l"(r) : "l"(a), "l"(b)); return r;
}
__device__ __forceinline__ ull pfma(ull a, ull b, ull c) {
    ull r; asm("fma.rn.f32x2 %0, %1, %2, %3;" : "=l"(r) : "l"(a), "l"(b), "l"(c)); return r;
}
__device__ __forceinline__ float frcpa(float x) {
    float r; asm("rcp.approx.f32 %0, %1;" : "=f"(r) : "f"(x)); return r;
}

__device__ __forceinline__ float2 cmulf(float2 a, float2 b) {
    return make_float2(a.x * b.x - a.y * b.y, a.x * b.y + a.y * b.x);
}
__device__ __forceinline__ float2 cadd(float2 a, float2 b) {
    union { float2 f; ull u; } A, B, R;
    A.f = a; B.f = b;
    asm("add.rn.f32x2 %0, %1, %2;" : "=l"(R.u) : "l"(A.u), "l"(B.u));
    return R.f;
}
__device__ __forceinline__ float2 csub(float2 a, float2 b) {
    union { float2 f; ull u; } A, B, R;
    A.f = a; B.f = b;
    asm("fma.rn.f32x2 %0, %1, %2, %3;"
        : "=l"(R.u) : "l"(B.u), "l"(0xBF800000BF800000ULL), "l"(A.u));
    return R.f;
}
__device__ __forceinline__ float2 cmulF(float2 v, float2 wn, float2 wr) {
    return make_float2(v.x * wn.x + v.y * wr.x, v.x * wn.y + v.y * wr.y);
}

template<bool FWD> __device__ __forceinline__ float2 mul_j(float2 a) {
    return FWD ? make_float2(a.y, -a.x) : make_float2(-a.y, a.x);
}
template<bool FWD> __device__ __forceinline__ float2 mul_w1(float2 a) {
    const float C = 0.70710678118654752f;
    return FWD ? make_float2(C * (a.x + a.y), C * (a.y - a.x))
               : make_float2(C * (a.x - a.y), C * (a.x + a.y));
}
template<bool FWD> __device__ __forceinline__ float2 mul_w3(float2 a) {
    const float C = 0.70710678118654752f;
    return FWD ? make_float2(C * (a.y - a.x), -C * (a.x + a.y))
               : make_float2(-C * (a.x + a.y), C * (a.x - a.y));
}

template<bool FWD>
__device__ __forceinline__ void fft8(float2* v) {
    float2 t0 = cadd(v[0], v[4]), t4 = csub(v[0], v[4]);
    float2 t1 = cadd(v[1], v[5]), t5 = mul_w1<FWD>(csub(v[1], v[5]));
    float2 t2 = cadd(v[2], v[6]), t6 = mul_j<FWD>(csub(v[2], v[6]));
    float2 t3 = cadd(v[3], v[7]), t7 = mul_w3<FWD>(csub(v[3], v[7]));
    float2 u0 = cadd(t0, t2), u2 = csub(t0, t2);
    float2 u1 = cadd(t1, t3), u3 = mul_j<FWD>(csub(t1, t3));
    float2 u4 = cadd(t4, t6), u6 = csub(t4, t6);
    float2 u5 = cadd(t5, t7), u7 = mul_j<FWD>(csub(t5, t7));
    v[0] = cadd(u0, u1); v[4] = csub(u0, u1);
    v[2] = cadd(u2, u3); v[6] = csub(u2, u3);
    v[1] = cadd(u4, u5); v[5] = csub(u4, u5);
    v[3] = cadd(u6, u7); v[7] = csub(u6, u7);
}

// forward fft8, inputs 4..7 == 0
__device__ __forceinline__ void fft8_z4(const float2* a, float2* v) {
    float2 t0 = a[0], t4 = a[0];
    float2 t1 = a[1], t5 = mul_w1<true>(a[1]);
    float2 t2 = a[2], t6 = mul_j<true>(a[2]);
    float2 t3 = a[3], t7 = mul_w3<true>(a[3]);
    float2 u0 = cadd(t0, t2), u2 = csub(t0, t2);
    float2 u1 = cadd(t1, t3), u3 = mul_j<true>(csub(t1, t3));
    float2 u4 = cadd(t4, t6), u6 = csub(t4, t6);
    float2 u5 = cadd(t5, t7), u7 = mul_j<true>(csub(t5, t7));
    v[0] = cadd(u0, u1); v[4] = csub(u0, u1);
    v[2] = cadd(u2, u3); v[6] = csub(u2, u3);
    v[1] = cadd(u4, u5); v[5] = csub(u4, u5);
    v[3] = cadd(u6, u7); v[7] = csub(u6, u7);
}

template<bool FWD>
__device__ __forceinline__ void fft4(float2* v) {
    float2 t0 = cadd(v[0], v[2]), t2 = csub(v[0], v[2]);
    float2 t1 = cadd(v[1], v[3]), t3 = mul_j<FWD>(csub(v[1], v[3]));
    v[0] = cadd(t0, t1); v[2] = csub(t0, t1);
    v[1] = cadd(t2, t3); v[3] = csub(t2, t3);
}

// ---------------- radix-16 building blocks (conv) ----------------
#define C16 0.92387953251128675613f
#define S16 0.38268343236508977173f

template<bool FWD>
__device__ __forceinline__ void fft16_combine(float2* E, float2* O, float2* v) {
    O[1] = cmulf(O[1], make_float2( C16, FWD ? -S16 :  S16));
    O[2] = mul_w1<FWD>(O[2]);
    O[3] = cmulf(O[3], make_float2( S16, FWD ? -C16 :  C16));
    O[4] = mul_j<FWD>(O[4]);
    O[5] = cmulf(O[5], make_float2(-S16, FWD ? -C16 :  C16));
    O[6] = mul_w3<FWD>(O[6]);
    O[7] = cmulf(O[7], make_float2(-C16, FWD ? -S16 :  S16));
#pragma unroll
    for (int k = 0; k < 8; k++) {
        v[k]     = cadd(E[k], O[k]);
        v[k + 8] = csub(E[k], O[k]);
    }
}

template<bool FWD>
__device__ __forceinline__ void fft16(float2* v) {
    float2 E[8] = {v[0], v[2], v[4], v[6], v[8], v[10], v[12], v[14]};
    float2 O[8] = {v[1], v[3], v[5], v[7], v[9], v[11], v[13], v[15]};
    fft8<FWD>(E); fft8<FWD>(O);
    fft16_combine<FWD>(E, O, v);
}

__device__ __forceinline__ void fft16_z8(const float2* x, float2* v) {
    float2 ein[4] = {x[0], x[2], x[4], x[6]};
    float2 oin[4] = {x[1], x[3], x[5], x[7]};
    float2 E[8], O[8];
    fft8_z4(ein, E);
    fft8_z4(oin, O);
    fft16_combine<true>(E, O, v);
}

__device__ __forceinline__ void fft16_lo8(float2* v, float2* o) {
    float2 E[8] = {v[0], v[2], v[4], v[6], v[8], v[10], v[12], v[14]};
    float2 O[8] = {v[1], v[3], v[5], v[7], v[9], v[11], v[13], v[15]};
    fft8<false>(E); fft8<false>(O);
    O[1] = cmulf(O[1], make_float2( C16,  S16));
    O[2] = mul_w1<false>(O[2]);
    O[3] = cmulf(O[3], make_float2( S16,  C16));
    O[4] = mul_j<false>(O[4]);
    O[5] = cmulf(O[5], make_float2(-S16,  C16));
    O[6] = mul_w3<false>(O[6]);
    O[7] = cmulf(O[7], make_float2(-C16,  S16));
#pragma unroll
    for (int k = 0; k < 8; k++) o[k] = cadd(E[k], O[k]);
}

// Computed twiddles: w1 = e^{-i*pi*base/(8*NS)} via MUFU; w2/w4/w8 by squaring.
// Replaces 4 LDG.128 per stage with fma/MUFU work (conv is L1-bound, fma idle).
template<bool INV>
__device__ __forceinline__ void twapply16c(float2* v, int base, float invNs8) {
    float ang = -PI_F * (float)base * invNs8;
    float sv, cv;
    __sincosf(ang, &sv, &cv);
    if (INV) sv = -sv;
    float2 w1n = make_float2(cv, sv),          w1r = make_float2(-sv, cv);
    float2 w2n = cmulF(w1n, w1n, w1r),         w2r = make_float2(-w2n.y, w2n.x);
    float2 w4n = cmulF(w2n, w2n, w2r),         w4r = make_float2(-w4n.y, w4n.x);
    float2 w8n = cmulF(w4n, w4n, w4r),         w8r = make_float2(-w8n.y, w8n.x);
    v[1] = cmulF(v[1], w1n, w1r);
    v[2] = cmulF(v[2], w2n, w2r);
    v[4] = cmulF(v[4], w4n, w4r);
    v[8] = cmulF(v[8], w8n, w8r);
    float2 w3n = cmulF(w2n, w1n, w1r), w3r = make_float2(-w3n.y, w3n.x);
    v[3] = cmulF(v[3], w3n, w3r);
    float2 w5n = cmulF(w4n, w1n, w1r), w5r = make_float2(-w5n.y, w5n.x);
    v[5] = cmulF(v[5], w5n, w5r);
    float2 w6n = cmulF(w4n, w2n, w2r), w6r = make_float2(-w6n.y, w6n.x);
    v[6] = cmulF(v[6], w6n, w6r);
    float2 w7n = cmulF(w4n, w3n, w3r), w7r = make_float2(-w7n.y, w7n.x);
    v[7] = cmulF(v[7], w7n, w7r);
    float2 w9n  = cmulF(w8n, w1n, w1r), w9r  = make_float2(-w9n.y,  w9n.x);
    v[9]  = cmulF(v[9],  w9n,  w9r);
    float2 w10n = cmulF(w8n, w2n, w2r), w10r = make_float2(-w10n.y, w10n.x);
    v[10] = cmulF(v[10], w10n, w10r);
    float2 w11n = cmulF(w8n, w3n, w3r), w11r = make_float2(-w11n.y, w11n.x);
    v[11] = cmulF(v[11], w11n, w11r);
    float2 w12n = cmulF(w8n, w4n, w4r), w12r = make_float2(-w12n.y, w12n.x);
    v[12] = cmulF(v[12], w12n, w12r);
    float2 w13n = cmulF(w8n, w5n, w5r), w13r = make_float2(-w13n.y, w13n.x);
    v[13] = cmulF(v[13], w13n, w13r);
    float2 w14n = cmulF(w8n, w6n, w6r), w14r = make_float2(-w14n.y, w14n.x);
    v[14] = cmulF(v[14], w14n, w14r);
    float2 w15n = cmulF(w8n, w7n, w7r), w15r = make_float2(-w15n.y, w15n.x);
    v[15] = cmulF(v[15], w15n, w15r);
}

template<int NS, bool INV>
__device__ __forceinline__ void stage16_ip(float2* s, int t) {
    float2 v[16];
#pragma unroll
    for (int r = 0; r < 16; r++) v[r] = s[SW16(t + 256 * r)];
    const int base = t & (NS - 1);
    twapply16c<INV>(v, base, 1.0f / (float)(8 * NS));
    fft16<!INV>(v);
    __syncthreads();
    const int idxD = ((t - base) << 4) + base;
#pragma unroll
    for (int r = 0; r < 16; r++) s[SW16(idxD + NS * r)] = v[r];
    __syncthreads();
}

// pointwise with P/M: Y = z*P + conj(zm)*M
__device__ __forceinline__ float2 pwone_pm(float2 z, float2 zm, float2 P, float2 M) {
    return make_float2(z.x * P.x - z.y * P.y + zm.x * M.x + zm.y * M.y,
                       z.x * P.y + z.y * P.x + zm.x * M.y - zm.y * M.x);
}

__device__ __forceinline__ void inv_stage0_pw16(float2* s, int t, const float4* Kp) {
    float2 v[16];
#pragma unroll
    for (int r = 0; r < 16; r++) {
        int e = t + 256 * r;
        float2 z  = s[SW16(e)];
        float2 zm = s[SW16((LFFT - e) & (LFFT - 1))];   // e=0 -> itself
        float4 K4 = Kp[e];
        v[r] = pwone_pm(z, zm, make_float2(K4.x, K4.y), make_float2(K4.z, K4.w));
    }
    fft16<false>(v);
    __syncthreads();
#pragma unroll
    for (int r = 0; r < 16; r++) s[SW16(16 * t + r)] = v[r];
    __syncthreads();
}

__global__ void init_twd_kernel() {
    int i = blockIdx.x * blockDim.x + threadIdx.x;
    if (i >= LFFT) return;
    if (i == 0) { g_twd[0] = make_float4(1.0f, 0.0f, 0.0f, 1.0f); return; }
    int k = 31 - __clz(i);
    int Ns = 1 << k;
    int base = i - Ns;
    float ang = -PI_F * (float)base / (float)Ns;
    float s, c;
    sincosf(ang, &s, &c);
    g_twd[i] = make_float4(c, s, -s, c);
}

// ---------------- t2 (output transpose) ----------------
__global__ void __launch_bounds__(256) t2_kernel(float* __restrict__ out) {
    __shared__ float2 tile[32][33];
    int pt = blockIdx.x * 32;
    int rt = blockIdx.y * 32;
    int tx = threadIdx.x & 31, ty = threadIdx.x >> 5;
    int b = rt >> 11, l0 = rt & (LSEQ - 1);
#pragma unroll
    for (int i = 0; i < 4; i++) {
        int p = pt + ty + i * 8;
        tile[ty + i * 8][tx] = g_yt[((size_t)(b * NPAIR + p)) * LSEQ + l0 + tx];
    }
    __syncthreads();
    float2* of2 = reinterpret_cast<float2*>(out);
#pragma unroll
    for (int i = 0; i < 4; i++) {
        int row = ty + i * 8;
        of2[(size_t)(rt + row) * NPAIR + pt + tx] = tile[tx][row];
    }
}

// dual-channel inverse FFT2048
__device__ void ifft2048_dual(float2* b0, float2* b1, int tid) {
    int ch = tid >> 8;
    int jt = tid & 255;
    float2* src = b0 + ch * 2048;
    float2* dst = b1 + ch * 2048;
#pragma unroll
    for (int s = 0; s < 3; s++) {
        const int Ns = 1 << (3 * s);
        {
            int j = jt;
            float2 v[8];
#pragma unroll
            for (int r = 0; r < 8; r++) v[r] = src[SWZ(j + r * 256)];
            const int base = j & (Ns - 1);
            if (Ns > 1) {
                float4 T1 = g_twd[4 * Ns + base];
                float4 T2 = g_twd[2 * Ns + base];
                float4 T4 = g_twd[Ns + base];
                float2 w1 = make_float2(T1.x, -T1.y);
                float2 w2 = make_float2(T2.x, -T2.y);
                float2 w4 = make_float2(T4.x, -T4.y);
                float2 w3 = cmulf(w1, w2), w5 = cmulf(w1, w4);
                float2 w6 = cmulf(w2, w4), w7 = cmulf(w3, w4);
                v[1] = cmulf(v[1], w1); v[2] = cmulf(v[2], w2); v[3] = cmulf(v[3], w3);
                v[4] = cmulf(v[4], w4); v[5] = cmulf(v[5], w5); v[6] = cmulf(v[6], w6);
                v[7] = cmulf(v[7], w7);
            }
            fft8<false>(v);
            const int idxD = ((j - base) << 3) + base;
#pragma unroll
            for (int r = 0; r < 8; r++) dst[SWZ(idxD + r * Ns)] = v[r];
        }
        __syncthreads();
        float2* t = src; src = dst; dst = t;
    }
#pragma unroll
    for (int q = 0; q < 2; q++) {
        int j = jt + q * 256;
        float2 v[4];
#pragma unroll
        for (int r = 0; r < 4; r++) v[r] = src[SWZ(j + r * 512)];
        float4 T1 = g_twd[1024 + j];
        float4 T2 = g_twd[512 + j];
        float2 w1 = make_float2(T1.x, -T1.y);
        float2 w2 = make_float2(T2.x, -T2.y);
        float2 w3 = cmulf(w1, w2);
        v[1] = cmulf(v[1], w1); v[2] = cmulf(v[2], w2); v[3] = cmulf(v[3], w3);
        fft4<false>(v);
#pragma unroll
        for (int r = 0; r < 4; r++) dst[SWZ(j + r * 512)] = v[r];
    }
    __syncthreads();
}

// P/M split for one (Z, Zm) pair -> float4 for bin k
__device__ __forceinline__ float4 pm_pack(float2 Z, float2 Zm, float invF) {
    float2 h0 = make_float2(0.5f * (Z.x + Zm.x), 0.5f * (Z.y - Zm.y));
    float2 dv = make_float2(Z.x - Zm.x, Z.y + Zm.y);
    float2 h1 = make_float2(0.5f * dv.y, -0.5f * dv.x);
    return make_float4((h0.x + h1.x) * invF, (h0.y + h1.y) * invF,
                       (h0.x - h1.x) * invF, (h0.y - h1.y) * invF);
}

// ---------------------------------------------------------------------------
// fused khat-pair + t1 (unchanged from R15)
// ---------------------------------------------------------------------------
__global__ void __launch_bounds__(512, 2) khat_t1_kernel(
    const float* __restrict__ pr, const float* __restrict__ qr,
    const float* __restrict__ lamr, const float* __restrict__ Br,
    const float* __restrict__ Ctr, const float* __restrict__ logstep,
    const float* __restrict__ u) {
    extern __shared__ float2 sm[];
    int tid = threadIdx.x;

    __shared__ float2 t1tile[2][32][33];        // t1 blocks only

    if (blockIdx.x >= NPAIR) {
        int fb   = blockIdx.x - NPAIR;
        int half = tid >> 8;
        int tid2 = tid & 255;
        int tileId = fb * 2 + half;
        int pt = (tileId & 7) * 32;
        int rt = (tileId >> 3) * 32;
        int tx = tid2 & 31, ty = tid2 >> 5;
        const float2* uf2 = reinterpret_cast<const float2*>(u);
#pragma unroll
        for (int i = 0; i < 4; i++) {
            int row = ty + i * 8;
            t1tile[half][row][tx] = uf2[(size_t)(rt + row) * NPAIR + pt + tx];
        }
        __syncthreads();
        int b = rt >> 11, l0 = rt & (LSEQ - 1);
#pragma unroll
        for (int i = 0; i < 4; i++) {
            int p = pt + ty + i * 8;
            g_ut[((size_t)(b * NPAIR + p)) * LSEQ + l0 + tx] = t1tile[half][tx][ty + i * 8];
        }
        return;
    }

    float2* buf0 = sm;
    float2* buf1 = sm + LFFT;

    __shared__ float2 w00[2][NSTATE], w01[2][NSTATE], w10[2][NSTATE], w11[2][NSTATE];
    __shared__ float2 lams[NSTATE];
    __shared__ float s_inv2step[2];

    int pidx = blockIdx.x;
    int d0 = pidx * 2;

    if (tid < 2 * NSTATE) {
        int ch = tid >> 6, n = tid & (NSTATE - 1);
        int d = d0 + ch;
        float2 p  = make_float2(pr[2*n],  pr[2*n+1]);
        float2 qc = make_float2(qr[2*n], -qr[2*n+1]);
        float2 Bv = make_float2(Br[(d*NSTATE+n)*2],  Br[(d*NSTATE+n)*2+1]);
        float2 Cc = make_float2(Ctr[(d*NSTATE+n)*2], -Ctr[(d*NSTATE+n)*2+1]);
        w00[ch][n] = cmulf(Cc, Bv);
        w01[ch][n] = cmulf(Cc, p);
        w10[ch][n] = cmulf(qc, Bv);
        w11[ch][n] = cmulf(qc, p);
        if (ch == 0) lams[n] = make_float2(lamr[2*n], lamr[2*n+1]);
    }
    if (tid < 2) s_inv2step[tid] = 2.0f * expf(-logstep[d0 + tid]);
    __syncthreads();

    float ts[4];
#pragma unroll
    for (int kk = 0; kk < 4; kk++) {
        int l = tid + kk * 512;
        ts[kk] = tanf((PI_F / (float)LSEQ) * (float)l);
    }

    for (int ch = 0; ch < 2; ch++) {
        float inv2step = s_inv2step[ch];
        ull Gp[2];
        Gp[0] = pk(-inv2step * ts[0], -inv2step * ts[1]);
        Gp[1] = pk(-inv2step * ts[2], -inv2step * ts[3]);

        ull a00x[2] = {0, 0}, a00y[2] = {0, 0};
        ull a01x[2] = {0, 0}, a01y[2] = {0, 0};
        ull a10x[2] = {0, 0}, a10y[2] = {0, 0};
        ull a11x[2] = {0, 0}, a11y[2] = {0, 0};
        const ull NEG1 = 0xBF800000BF800000ULL;

        for (int n = 0; n < NSTATE; n++) {
            float2 lw  = lams[n];
            float2 v00 = w00[ch][n], v01 = w01[ch][n];
            float2 v10 = w10[ch][n], v11 = w11[ch][n];
            float dr = -lw.x;
            ull nlwy = pk(-lw.y, -lw.y);
            ull drp  = pk(dr, dr);
            ull drsq = pk(dr * dr, dr * dr);
            ull x00 = pk(v00.x, v00.x), y00 = pk(v00.y, v00.y);
            ull x01 = pk(v01.x, v01.x), y01 = pk(v01.y, v01.y);
            ull x10 = pk(v10.x, v10.x), y10 = pk(v10.y, v10.y);
            ull x11 = pk(v11.x, v11.x), y11 = pk(v11.y, v11.y);
#pragma unroll
            for (int j = 0; j < 2; j++) {
                ull dip = padd(Gp[j], nlwy);
                ull mag = pfma(dip, dip, drsq);
                float m0, m1;
                upk(mag, m0, m1);
                ull invp = pk(frcpa(m0), frcpa(m1));
                ull sx  = pmul(drp, invp);
                ull ty  = pmul(dip, invp);
                ull nty = pmul(ty, NEG1);
                a00x[j] = pfma(x00, sx, a00x[j]); a00x[j] = pfma(y00, ty,  a00x[j]);
                a00y[j] = pfma(y00, sx, a00y[j]); a00y[j] = pfma(x00, nty, a00y[j]);
                a01x[j] = pfma(x01, sx, a01x[j]); a01x[j] = pfma(y01, ty,  a01x[j]);
                a01y[j] = pfma(y01, sx, a01y[j]); a01y[j] = pfma(x01, nty, a01y[j]);
                a10x[j] = pfma(x10, sx, a10x[j]); a10x[j] = pfma(y10, ty,  a10x[j]);
                a10y[j] = pfma(y10, sx, a10y[j]); a10y[j] = pfma(x10, nty, a10y[j]);
                a11x[j] = pfma(x11, sx, a11x[j]); a11x[j] = pfma(y11, ty,  a11x[j]);
                a11y[j] = pfma(y11, sx, a11y[j]); a11y[j] = pfma(x11, nty, a11y[j]);
            }
        }

        float2* dstb = buf0 + ch * 2048;
#pragma unroll
        for (int j = 0; j < 2; j++) {
            float x0, x1, y0, y1;
            float2 A00[2], A01[2], A10[2], A11[2];
            upk(a00x[j], x0, x1); upk(a00y[j], y0, y1);
            A00[0] = make_float2(x0, y0); A00[1] = make_float2(x1, y1);
            upk(a01x[j], x0, x1); upk(a01y[j], y0, y1);
            A01[0] = make_float2(x0, y0); A01[1] = make_float2(x1, y1);
            upk(a10x[j], x0, x1); upk(a10y[j], y0, y1);
            A10[0] = make_float2(x0, y0); A10[1] = make_float2(x1, y1);
            upk(a11x[j], x0, x1); upk(a11y[j], y0, y1);
            A11[0] = make_float2(x0, y0); A11[1] = make_float2(x1, y1);
#pragma unroll
            for (int slot = 0; slot < 2; slot++) {
                int kk = 2 * j + slot;
                int l = tid + kk * 512;
                float2 den = make_float2(1.0f + A11[slot].x, A11[slot].y);
                float dinv = __fdividef(1.0f, den.x * den.x + den.y * den.y);
                float2 num = cmulf(A01[slot], A10[slot]);
                float2 frac = make_float2((num.x * den.x + num.y * den.y) * dinv,
                                          (num.y * den.x - num.x * den.y) * dinv);
                float2 inner = make_float2(A00[slot].x - frac.x, A00[slot].y - frac.y);
                float2 c = make_float2(1.0f, -ts[kk]);
                dstb[SWZ(l)] = cmulf(c, inner);
            }
        }
    }
    __syncthreads();

    ifft2048_dual(buf0, buf1, tid);

    // fused: K-pair extraction + fft4096 stage 0 (top half zero), buf0 -> buf1
    const float invL = 1.0f / (float)LSEQ;
    {
        float2 a[4], v[8];
#pragma unroll
        for (int r = 0; r < 4; r++) {
            int m = tid + 512 * r;
            int rm = (LSEQ - m) & (LSEQ - 1);
            a[r] = make_float2(buf0[SWZ(rm)].x * invL,
                               buf0[2048 + SWZ(rm)].x * invL);
        }
        fft8_z4(a, v);
        int idxD = tid << 3;
#pragma unroll
        for (int r = 0; r < 8; r++) buf1[SWZ(idxD + r)] = v[r];
    }
    __syncthreads();

    // fft4096 stages 1..3 (Ns = 8, 64, 512)
    float2* srcb = buf1;
    float2* dstb2 = buf0;
#pragma unroll
    for (int s = 1; s < 4; s++) {
        const int Ns = 1 << (3 * s);
        int j = tid;
        float2 v[8];
#pragma unroll
        for (int r = 0; r < 8; r++) v[r] = srcb[SWZ(j + r * 512)];
        const int base = j & (Ns - 1);
        {
            float4 T1 = g_twd[4 * Ns + base];
            float4 T2 = g_twd[2 * Ns + base];
            float4 T4 = g_twd[Ns + base];
            float2 w1 = make_float2(T1.x, T1.y);
            float2 w2 = make_float2(T2.x, T2.y);
            float2 w4 = make_float2(T4.x, T4.y);
            float2 w3 = cmulf(w1, w2), w5 = cmulf(w1, w4);
            float2 w6 = cmulf(w2, w4), w7 = cmulf(w3, w4);
            v[1] = cmulf(v[1], w1); v[2] = cmulf(v[2], w2); v[3] = cmulf(v[3], w3);
            v[4] = cmulf(v[4], w4); v[5] = cmulf(v[5], w5); v[6] = cmulf(v[6], w6);
            v[7] = cmulf(v[7], w7);
        }
        fft8<true>(v);
        const int idxD = ((j - base) << 3) + base;
#pragma unroll
        for (int r = 0; r < 8; r++) dstb2[SWZ(idxD + r * Ns)] = v[r];
        __syncthreads();
        float2* tmp = srcb; srcb = dstb2; dstb2 = tmp;
    }
    float2* resZ = srcb;   // buf0 after 3 swaps

    // half-range P/M split
    const float invF = 0.5f / (float)LFFT;
    float4* KP4 = g_KPM4 + (size_t)pidx * LFFT;
    for (int k = tid; k < 2048; k += 512) {
        float2 Z  = resZ[SWZ(k)];
        int km = (LFFT - k) & (LFFT - 1);
        float2 Zm = resZ[SWZ(km)];
        KP4[k] = pm_pack(Z, Zm, invF);
        if (k != 0) KP4[km] = pm_pack(Zm, Z, invF);
    }
    if (tid == 0) {
        float2 Z = resZ[SWZ(2048)];
        KP4[2048] = pm_pack(Z, Z, invF);
    }
}

// ---------------------------------------------------------------------------
// conv: in-place radix-16, 3 CTAs/SM; twiddles COMPUTED (MUFU+fma), no g_twd reads
// ---------------------------------------------------------------------------
__global__ void __launch_bounds__(256, 3) conv_kernel(const float* __restrict__ Dvec) {
    extern __shared__ float2 s[];   // 4096 float2 = 32KB

    int t    = threadIdx.x;
    int blk  = blockIdx.x;
    int pair = blk & (NPAIR - 1);
    int b    = blk >> 8;
    int d0   = pair * 2;

    const float2* ut = g_ut + ((size_t)(b * NPAIR + pair)) * LSEQ;
    float2*       yt = g_yt + ((size_t)(b * NPAIR + pair)) * LSEQ;

    {
        float2 x[8], v[16];
#pragma unroll
        for (int r = 0; r < 8; r++) x[r] = ut[t + 256 * r];
        fft16_z8(x, v);
#pragma unroll
        for (int r = 0; r < 16; r++) s[SW16(16 * t + r)] = v[r];
        __syncthreads();
    }

    stage16_ip<16,  false>(s, t);
    stage16_ip<256, false>(s, t);

    inv_stage0_pw16(s, t, g_KPM4 + (size_t)pair * LFFT);

    stage16_ip<16, true>(s, t);

    // final inverse stage (Ns=256), outputs 0..7 only, streamed to global
    {
        float2 v[16];
#pragma unroll
        for (int r = 0; r < 16; r++) v[r] = s[SW16(t + 256 * r)];
        twapply16c<true>(v, t, 1.0f / 2048.0f);
        float2 o[8];
        fft16_lo8(v, o);

        float D0 = Dvec[d0], D1 = Dvec[d0 + 1];
#pragma unroll
        for (int r = 0; r < 8; r++) {
            float2 uv = ut[t + 256 * r];
            yt[t + 256 * r] = make_float2(o[r].x + D0 * uv.x, o[r].y + D1 * uv.y);
        }
    }
}

// ---------------------------------------------------------------------------
// Inputs: u, p_ri, q_ri, lam_ri, B_ri, Ct_ri, D, log_step
// ---------------------------------------------------------------------------
extern "C" void kernel_launch(void* const* d_in, const int* in_sizes, int n_in,
                              void* d_out, int out_size) {
    const float* u   = (const float*)d_in[0];
    const float* pr  = (const float*)d_in[1];
    const float* qr  = (const float*)d_in[2];
    const float* lam = (const float*)d_in[3];
    const float* Br  = (const float*)d_in[4];
    const float* Ct  = (const float*)d_in[5];
    const float* Dv  = (const float*)d_in[6];
    const float* ls  = (const float*)d_in[7];
    float* out = (float*)d_out;

    const int smem_khat = 2 * LFFT * (int)sizeof(float2);   // 64 KB
    const int smem_conv = LFFT * (int)sizeof(float2);       // 32 KB
    cudaFuncSetAttribute(khat_t1_kernel, cudaFuncAttributeMaxDynamicSharedMemorySize, smem_khat);
    cudaFuncSetAttribute(conv_kernel,   cudaFuncAttributeMaxDynamicSharedMemorySize, smem_conv);

    init_twd_kernel<<<LFFT / 512, 512>>>();                                            // 0
    khat_t1_kernel<<<NPAIR + 4096, 512, smem_khat>>>(pr, qr, lam, Br, Ct, ls, u);      // 1
    conv_kernel<<<NBATCH * NPAIR, 256, smem_conv>>>(Dv);                                // 2
    t2_kernel<<<dim3(NPAIR / 32, NBATCH * LSEQ / 32), 256>>>(out);                      // 3
}